// round 11
// baseline (speedup 1.0000x reference)
#include <cuda_runtime.h>
#include <cuda_fp16.h>
#include <cuda_bf16.h>
#include <cstdint>

// ---------------------------------------------------------------------------
// Problem constants
// ---------------------------------------------------------------------------
constexpr int IN_F    = 4096;    // K
constexpr int OUT_F   = 4096;    // N
constexpr int M_TOTAL = 8192;    // M

// GEMM tiling: CTA 128x128x64. 4 consumer warps (2x2, warp tile 64x64) +
// 1 producer warp. 3-stage mbarrier ring. 2 CTAs/SM.
// B travels as packed 4-bit and is dequantized in consumer registers.
constexpr int BM = 128, BN = 128, BK = 64;
constexpr int STAGES = 3;
constexpr int NSTG   = IN_F / BK;        // 64
constexpr int LDR    = 72;               // A smem row stride in halfs (144B)
constexpr int LDR2   = LDR * 2;          // bytes
constexpr int A_BYTES     = BM * LDR2;               // 18432
constexpr int BQ_BYTES    = 2 * BN * 16;             // 4096 (2 ktp x 128 n x 16B)
constexpr int STAGE_BYTES = A_BYTES + BQ_BYTES;      // 22528

constexpr int SM_FULL   = 0;      // 3 x 8B full mbarriers
constexpr int SM_EMPTY  = 32;     // 3 x 8B empty mbarriers
constexpr int SM_SZ     = 64;     // 2 x 512B scale/zero buffers (per-group)
constexpr int SM_STAGE0 = 1152;
constexpr int SMEM_TOTAL = SM_STAGE0 + STAGES * STAGE_BYTES;   // 68736

constexpr int THREADS = 160;      // 4 consumer warps + 1 producer warp

// Scratch (__device__ globals = allowed scratch)
__device__ __half g_X [(size_t)M_TOTAL * IN_F];   // canonical fp16 x  (64MB)
__device__ uint4  g_Bq[(size_t)(IN_F / 32) * OUT_F]; // repacked 4-bit B (8MB)
__device__ int    g_mode;                         // 0=f32, 1=fp16, 2=bf16 buffers

// ---------------------------------------------------------------------------
// helpers
// ---------------------------------------------------------------------------
__device__ __forceinline__ float dec_h(unsigned short v) {
    __half_raw h; h.x = v; return __half2float(__half(h));
}
__device__ __forceinline__ float dec_b(unsigned short v) {
    __nv_bfloat16_raw r; r.x = v; return __bfloat162float(__nv_bfloat16(r));
}
__device__ __forceinline__ unsigned short enc_h(float f) {
    __half h = __float2half(f); return reinterpret_cast<unsigned short&>(h);
}
__device__ __forceinline__ unsigned short enc_b(float f) {
    __nv_bfloat16 b = __float2bfloat16(f); return reinterpret_cast<unsigned short&>(b);
}
__device__ __forceinline__ void cp16(uint32_t saddr, const void* g) {
    asm volatile("cp.async.cg.shared.global [%0], [%1], 16;\n" :: "r"(saddr), "l"(g));
}
__device__ __forceinline__ void ldsm4(uint32_t* r, uint32_t addr) {
    asm volatile("ldmatrix.sync.aligned.m8n8.x4.shared.b16 {%0,%1,%2,%3}, [%4];\n"
                 : "=r"(r[0]), "=r"(r[1]), "=r"(r[2]), "=r"(r[3]) : "r"(addr));
}
__device__ __forceinline__ void mma16816(float* c, const uint32_t* a,
                                         uint32_t b0, uint32_t b1) {
    asm volatile(
        "mma.sync.aligned.m16n8k16.row.col.f32.f16.f16.f32 "
        "{%0,%1,%2,%3}, {%4,%5,%6,%7}, {%8,%9}, {%0,%1,%2,%3};\n"
        : "+f"(c[0]), "+f"(c[1]), "+f"(c[2]), "+f"(c[3])
        : "r"(a[0]), "r"(a[1]), "r"(a[2]), "r"(a[3]), "r"(b0), "r"(b1));
}
__device__ __forceinline__ void mbar_init(uint32_t a, uint32_t cnt) {
    asm volatile("mbarrier.init.shared.b64 [%0], %1;\n" :: "r"(a), "r"(cnt) : "memory");
}
__device__ __forceinline__ void mbar_arrive(uint32_t a) {
    asm volatile("mbarrier.arrive.shared.b64 _, [%0];\n" :: "r"(a) : "memory");
}
// .noinc required (round-9 lesson): default form bumps expected count -> hang.
__device__ __forceinline__ void cp_async_mbar_arrive(uint32_t a) {
    asm volatile("cp.async.mbarrier.arrive.noinc.shared.b64 [%0];\n" :: "r"(a) : "memory");
}
__device__ __forceinline__ void mbar_wait(uint32_t a, uint32_t parity) {
    uint32_t done;
    asm volatile("{\n\t.reg .pred p;\n\t"
        "mbarrier.try_wait.parity.acquire.cta.shared::cta.b64 p, [%1], %2;\n\t"
        "selp.b32 %0, 1, 0, p;\n\t}" : "=r"(done) : "r"(a), "r"(parity) : "memory");
    if (!done) {
        asm volatile("{\n\t.reg .pred P1;\n\t"
            "W%=:\n\t"
            "mbarrier.try_wait.parity.acquire.cta.shared::cta.b64 P1, [%0], %1, 0x989680;\n\t"
            "@P1 bra.uni D%=;\n\t"
            "bra.uni W%=;\n\t"
            "D%=:\n\t}" :: "r"(a), "r"(parity) : "memory");
    }
}
__device__ __forceinline__ uint32_t lds32(uint32_t addr) {
    uint32_t v;
    asm volatile("ld.shared.b32 %0, [%1];" : "=r"(v) : "r"(addr));
    return v;
}
__device__ __forceinline__ void sts32(uint32_t addr, uint32_t v) {
    asm volatile("st.shared.b32 [%0], %1;" :: "r"(addr), "r"(v) : "memory");
}

// ---------------------------------------------------------------------------
// Kernel 0: dtype probe on scales (true values in (0.001, 0.011]).
// ---------------------------------------------------------------------------
__global__ void detect_kernel(const void* scales) {
    const unsigned short* su = (const unsigned short*)scales;
    int c16 = 0, cbf = 0;
    for (int i = 0; i < 64; i++) {
        float vh = dec_h(su[i]); if (vh > 0.0005f && vh < 0.02f) c16++;
        float vb = dec_b(su[i]); if (vb > 0.0005f && vb < 0.02f) cbf++;
    }
    g_mode = (c16 >= 48) ? 1 : ((cbf >= 48) ? 2 : 0);
}

// ---------------------------------------------------------------------------
// Kernel 1: canonicalize x -> fp16 g_X (8 elems/thread)
// ---------------------------------------------------------------------------
__global__ void convert_x_kernel(const void* __restrict__ x_raw) {
    const int mode = g_mode;
    const size_t i8 = (size_t)blockIdx.x * blockDim.x + threadIdx.x;
    __half out[8];
    if (mode == 0) {
        const float4* xf = (const float4*)x_raw;
        const float4 a = xf[i8 * 2 + 0];
        const float4 b = xf[i8 * 2 + 1];
        out[0] = __float2half(a.x); out[1] = __float2half(a.y);
        out[2] = __float2half(a.z); out[3] = __float2half(a.w);
        out[4] = __float2half(b.x); out[5] = __float2half(b.y);
        out[6] = __float2half(b.z); out[7] = __float2half(b.w);
    } else {
        const uint4 v = ((const uint4*)x_raw)[i8];
        const unsigned int w[4] = {v.x, v.y, v.z, v.w};
        if (mode == 1) {
            *reinterpret_cast<uint4*>(out) = v;
        } else {
#pragma unroll
            for (int k = 0; k < 4; k++) {
                out[2*k+0] = __float2half(dec_b((unsigned short)(w[k] & 0xFFFF)));
                out[2*k+1] = __float2half(dec_b((unsigned short)(w[k] >> 16)));
            }
        }
    }
    *reinterpret_cast<uint4*>(&g_X[i8 * 8]) = *reinterpret_cast<const uint4*>(out);
}

// ---------------------------------------------------------------------------
// Kernel 2: repack 4-bit qweight into fragment-friendly words.
// Word w(ktp, n, cg) nibble map (k base = 32*ktp, c0 = 2*cg):
//   bits[ 0: 4)=nib(c0)      [ 4: 8)=nib(c0+8)    [ 8:12)=nib(16+c0)  [12:16)=nib(24+c0)
//   bits[16:20)=nib(c0+1)    [20:24)=nib(c0+9)    [24:28)=nib(16+c0+1)[28:32)=nib(24+c0+1)
// Consumer then gets an mma B-fragment reg via one shift+LOP3:
//   b(reg) = ((w >> sh) & 0x000F000F) | 0x64006400   (fp16 pair = 1024+q)
// ---------------------------------------------------------------------------
__global__ void repack_kernel(const int32_t* __restrict__ qweight) {
    const int n   = blockIdx.x * 256 + threadIdx.x;   // 0..4095
    const int ktp = blockIdx.y;                        // 0..127
    const uint32_t q0 = (uint32_t)qweight[(size_t)(ktp * 4 + 0) * OUT_F + n];
    const uint32_t q1 = (uint32_t)qweight[(size_t)(ktp * 4 + 1) * OUT_F + n];
    const uint32_t q2 = (uint32_t)qweight[(size_t)(ktp * 4 + 2) * OUT_F + n];
    const uint32_t q3 = (uint32_t)qweight[(size_t)(ktp * 4 + 3) * OUT_F + n];
    uint32_t out[4];
#pragma unroll
    for (int cg = 0; cg < 4; cg++) {
        const int sh = 8 * cg;
        out[cg] = (((q0 >> sh) & 0xF))
                | (((q1 >> sh) & 0xF) << 4)
                | (((q2 >> sh) & 0xF) << 8)
                | (((q3 >> sh) & 0xF) << 12)
                | (((q0 >> (sh + 4)) & 0xF) << 16)
                | (((q1 >> (sh + 4)) & 0xF) << 20)
                | (((q2 >> (sh + 4)) & 0xF) << 24)
                | (((q3 >> (sh + 4)) & 0xF) << 28);
    }
    g_Bq[(size_t)ktp * OUT_F + n] = make_uint4(out[0], out[1], out[2], out[3]);
}

// ---------------------------------------------------------------------------
// Kernel 3: fused 4-bit GEMM.
// Warps 0-3: consumers (ldsm A + in-reg B dequant + mma).
// Warp 4: producer (cp.async A fp16 + packed B + per-group scale/zero decode).
// ---------------------------------------------------------------------------
__global__ void __launch_bounds__(THREADS, 2)
gemm_kernel(const void* __restrict__ scales_raw,
            const int32_t* __restrict__ qzeros,
            const void* __restrict__ bias_raw,
            void* __restrict__ out_raw) {
    extern __shared__ __align__(128) unsigned char smem[];
    const uint32_t sbase = (uint32_t)__cvta_generic_to_shared(smem);

    const int tid  = threadIdx.x;     // 0..159
    const int wid  = tid >> 5;        // 0..4
    const int lane = tid & 31;
    const int mode = g_mode;

    const int m0 = blockIdx.x * BM;
    const int n0 = blockIdx.y * BN;

    if (tid == 0) {
#pragma unroll
        for (int s = 0; s < STAGES; s++) {
            mbar_init(sbase + SM_FULL  + s * 8, 64);    // 32 cp-arrive + 32 arrive
            mbar_init(sbase + SM_EMPTY + s * 8, 128);   // 128 consumer threads
        }
    }
    __syncthreads();

    if (wid == 4) {
        // ---------------------- producer (warp 4) --------------------------
        const __half* gA0 = g_X + (size_t)(m0 + (lane >> 3)) * IN_F + (lane & 7) * 8;
        const uint32_t sA0 = (uint32_t)((lane >> 3) * LDR2 + (lane & 7) * 16);
        uint32_t koff = 0;

        for (int s = 0; s < NSTG; s++) {
            const int buf = s % STAGES;
            const uint32_t par = 1u ^ (uint32_t)((s / STAGES) & 1);
            mbar_wait(sbase + SM_EMPTY + buf * 8, par);
            const uint32_t st = sbase + SM_STAGE0 + buf * STAGE_BYTES;

            // A: 128 rows x 64 halfs, 32 cp16/thread
#pragma unroll
            for (int t = 0; t < 32; t++)
                cp16(st + sA0 + t * (4 * LDR2), gA0 + koff + t * (4 * IN_F));

            // Bq: 2 ktp rows x 128 n x 16B, 8 cp16/thread
            const uint4* bsrc = g_Bq + (size_t)(s * 2) * OUT_F + n0;
#pragma unroll
            for (int tl = 0; tl < 2; tl++)
#pragma unroll
                for (int t = 0; t < 4; t++)
                    cp16(st + A_BYTES + tl * 2048 + (lane + t * 32) * 16,
                         bsrc + (size_t)tl * OUT_F + lane + t * 32);

            // scales/zeros for group g = s/2 (every other stage)
            if ((s & 1) == 0) {
                const int g = s >> 1;
                const uint32_t szb = sbase + SM_SZ + (g & 1) * 512;
#pragma unroll
                for (int t = 0; t < 4; t++) {
                    const int nl = lane + t * 32;
                    const int n  = n0 + nl;
                    float sf;
                    if (mode == 0)      sf = ((const float*)scales_raw)[(size_t)g * OUT_F + n];
                    else if (mode == 1) sf = dec_h(((const unsigned short*)scales_raw)[(size_t)g * OUT_F + n]);
                    else                sf = dec_b(((const unsigned short*)scales_raw)[(size_t)g * OUT_F + n]);
                    const uint32_t z = ((uint32_t)qzeros[(size_t)g * (OUT_F >> 3) + (n >> 3)]
                                        >> ((n & 7) << 2)) & 0xF;
                    const uint32_t word = ((0x6400u | z) << 16) | (uint32_t)enc_h(sf);
                    sts32(szb + nl * 4, word);
                }
            }
            cp_async_mbar_arrive(sbase + SM_FULL + buf * 8);
            mbar_arrive(sbase + SM_FULL + buf * 8);
            koff += BK;
        }
        return;
    }

    // ------------------------- consumers (warps 0-3) -----------------------
    const int wm = wid >> 1;          // 0..1 (64-row stripe)
    const int wn = wid & 1;           // 0..1 (64-col stripe)

    const int l15  = lane & 15;
    const int lsel = (lane >> 4) * 16;
    const uint32_t a_off = (uint32_t)(wm * 64 + l15) * LDR2 + lsel;

    float acc[4][8][4];
#pragma unroll
    for (int i = 0; i < 4; i++)
#pragma unroll
        for (int j = 0; j < 8; j++)
#pragma unroll
            for (int k = 0; k < 4; k++) acc[i][j][k] = 0.0f;

    uint32_t s2[8], d2[8];

    for (int s = 0; s < NSTG; s++) {
        const int buf = s % STAGES;
        const uint32_t par = (uint32_t)((s / STAGES) & 1);
        mbar_wait(sbase + SM_FULL + buf * 8, par);

        const uint32_t st = sbase + SM_STAGE0 + buf * STAGE_BYTES;
        const uint32_t bq = st + A_BYTES;

        if ((s & 1) == 0) {
            const int g = s >> 1;
            const uint32_t szb = sbase + SM_SZ + (g & 1) * 512;
#pragma unroll
            for (int nj = 0; nj < 8; nj++) {
                const uint32_t w = lds32(szb + (wn * 64 + nj * 8 + (lane >> 2)) * 4);
                s2[nj] = __byte_perm(w, w, 0x1010);   // (s, s)
                d2[nj] = __byte_perm(w, w, 0x3232);   // (1024+z, 1024+z)
            }
        }

#pragma unroll
        for (int ktp = 0; ktp < 2; ktp++) {
            uint32_t w[8];
#pragma unroll
            for (int nj = 0; nj < 8; nj++)
                w[nj] = lds32(bq + ktp * 2048 + (wn * 256 + nj * 32 + lane) * 4);

#pragma unroll
            for (int h = 0; h < 2; h++) {
                uint32_t bfr[8][2];
#pragma unroll
                for (int nj = 0; nj < 8; nj++) {
                    uint32_t b0 = ((w[nj] >> (8 * h))     & 0x000F000Fu) | 0x64006400u;
                    uint32_t b1 = ((w[nj] >> (8 * h + 4)) & 0x000F000Fu) | 0x64006400u;
                    asm("sub.rn.f16x2 %0, %0, %1;" : "+r"(b0) : "r"(d2[nj]));  // exact q-z
                    asm("mul.rn.f16x2 %0, %0, %1;" : "+r"(b0) : "r"(s2[nj]));
                    asm("sub.rn.f16x2 %0, %0, %1;" : "+r"(b1) : "r"(d2[nj]));
                    asm("mul.rn.f16x2 %0, %0, %1;" : "+r"(b1) : "r"(s2[nj]));
                    bfr[nj][0] = b0; bfr[nj][1] = b1;
                }
                const int kt = ktp * 2 + h;
#pragma unroll
                for (int mi = 0; mi < 4; mi++) {
                    uint32_t af[4];
                    ldsm4(af, st + a_off + mi * (16 * LDR2) + kt * 32);
#pragma unroll
                    for (int nj = 0; nj < 8; nj++)
                        mma16816(acc[mi][nj], af, bfr[nj][0], bfr[nj][1]);
                }
            }
        }
        mbar_arrive(sbase + SM_EMPTY + buf * 8);
    }

    // ---- epilogue: direct register -> global with fused bias ----
    const int mrow = m0 + wm * 64 + (lane >> 2);
    const int ncol = n0 + wn * 64 + (lane & 3) * 2;

    float bl[8], bh[8];
#pragma unroll
    for (int j = 0; j < 8; j++) {
        const int c = ncol + j * 8;
        if (mode == 0) {
            bl[j] = ((const float*)bias_raw)[c];
            bh[j] = ((const float*)bias_raw)[c + 1];
        } else if (mode == 1) {
            bl[j] = dec_h(((const unsigned short*)bias_raw)[c]);
            bh[j] = dec_h(((const unsigned short*)bias_raw)[c + 1]);
        } else {
            bl[j] = dec_b(((const unsigned short*)bias_raw)[c]);
            bh[j] = dec_b(((const unsigned short*)bias_raw)[c + 1]);
        }
    }

#pragma unroll
    for (int mi = 0; mi < 4; mi++) {
        const int r0 = mrow + mi * 16;
#pragma unroll
        for (int j = 0; j < 8; j++) {
            const int c = ncol + j * 8;
            const float v0 = acc[mi][j][0] + bl[j];
            const float v1 = acc[mi][j][1] + bh[j];
            const float v2 = acc[mi][j][2] + bl[j];
            const float v3 = acc[mi][j][3] + bh[j];
            if (mode == 0) {
                float2 p0, p1;
                p0.x = __half2float(__float2half(v0));
                p0.y = __half2float(__float2half(v1));
                p1.x = __half2float(__float2half(v2));
                p1.y = __half2float(__float2half(v3));
                *reinterpret_cast<float2*>((float*)out_raw + (size_t)r0 * OUT_F + c) = p0;
                *reinterpret_cast<float2*>((float*)out_raw + (size_t)(r0 + 8) * OUT_F + c) = p1;
            } else if (mode == 1) {
                uint32_t p0 = (uint32_t)enc_h(v0) | ((uint32_t)enc_h(v1) << 16);
                uint32_t p1 = (uint32_t)enc_h(v2) | ((uint32_t)enc_h(v3) << 16);
                *reinterpret_cast<uint32_t*>((unsigned short*)out_raw + (size_t)r0 * OUT_F + c) = p0;
                *reinterpret_cast<uint32_t*>((unsigned short*)out_raw + (size_t)(r0 + 8) * OUT_F + c) = p1;
            } else {
                uint32_t p0 = (uint32_t)enc_b(v0) | ((uint32_t)enc_b(v1) << 16);
                uint32_t p1 = (uint32_t)enc_b(v2) | ((uint32_t)enc_b(v3) << 16);
                *reinterpret_cast<uint32_t*>((unsigned short*)out_raw + (size_t)r0 * OUT_F + c) = p0;
                *reinterpret_cast<uint32_t*>((unsigned short*)out_raw + (size_t)(r0 + 8) * OUT_F + c) = p1;
            }
        }
    }
}

// ---------------------------------------------------------------------------
// Launch
// ---------------------------------------------------------------------------
extern "C" void kernel_launch(void* const* d_in, const int* in_sizes, int n_in,
                              void* d_out, int out_size) {
    const void*    x       = d_in[0];
    const int32_t* qweight = (const int32_t*)d_in[1];
    const int32_t* qzeros  = (const int32_t*)d_in[2];
    const void*    scales  = d_in[3];
    const void*    bias    = d_in[4];

    detect_kernel<<<1, 1>>>(scales);

    const unsigned nchunks = (unsigned)((size_t)M_TOTAL * IN_F / 8);
    convert_x_kernel<<<nchunks / 256, 256>>>(x);

    repack_kernel<<<dim3(OUT_F / 256, IN_F / 32), 256>>>(qweight);

    cudaFuncSetAttribute(gemm_kernel,
                         cudaFuncAttributeMaxDynamicSharedMemorySize, SMEM_TOTAL);
    dim3 grid(M_TOTAL / BM, OUT_F / BN);    // (64, 32)
    gemm_kernel<<<grid, THREADS, SMEM_TOTAL>>>(scales, qzeros, bias, d_out);
}